// round 17
// baseline (speedup 1.0000x reference)
#include <cuda_runtime.h>
#include <cuda_bf16.h>
#include <cuda_fp16.h>
#include <mma.h>
#include <cstdint>

using namespace nvcuda;

// Problem constants
#define N_NODES  100000
#define E_EDGES  1600000
#define M_EDGES  (E_EDGES + N_NODES)   // 1,700,000 with self loops
#define IN_DIM   128
#define D_DIM    128
#define H_HEADS  4
#define C_CH     32

// ---------------- device scratch ----------------
__device__ float  g_hin[N_NODES * D_DIM];
__device__ __half g_xp [N_NODES * D_DIM];   // fp16 payload: only consumed by edge gather
__device__ float  g_asrc[N_NODES * H_HEADS];
__device__ float  g_adst[N_NODES * H_HEADS];
__device__ int    g_cnt[N_NODES];
__device__ int    g_rowstart[N_NODES];
__device__ int    g_cursor[N_NODES];
__device__ int    g_csr[M_EDGES];
__device__ int    g_blksum[256];
__device__ int    g_blkoff[256];
__device__ float  g_colsum[D_DIM];
__device__ float  g_colsumsq[D_DIM];

__device__ __forceinline__ float lrelu02(float v) { return v > 0.f ? v : 0.2f * v; }

// ---------------- K0: init (runs on edge branch; also zeroes BN accumulators) ----------------
__global__ void init_kernel() {
    int i = blockIdx.x * blockDim.x + threadIdx.x;
    if (i < N_NODES) g_cnt[i] = 0;
    if (i < D_DIM) { g_colsum[i] = 0.f; g_colsumsq[i] = 0.f; }
}

// ---------------- K1: wmma fp16 GEMM (fp32 accum) + fused attention logits ----------------
// grid = (ceil(N/64), 2): y=0 -> h_in = x@lin_w + lin_b ; y=1 -> xp(fp16) = x@gat_w, + logits.
// Block 256 thr (8 warps). BM=64, BN=128, full K=128 resident in smem as fp16.
#define LDH   136   // half stride (128 + 8)
#define LDC_S 132   // float stride for C staging (64 rows)
#define XS_HALFS (64 * LDH)
#define WS_HALFS (128 * LDH)
#define GEMM_SMEM ((XS_HALFS + WS_HALFS) * 2)   // 52224 B (cs float reuse = 33792 B)

__global__ __launch_bounds__(256) void gemm_kernel(
    const float* __restrict__ x, const float* __restrict__ lin_w,
    const float* __restrict__ lin_b, const float* __restrict__ gat_w,
    const float* __restrict__ att_src, const float* __restrict__ att_dst)
{
    extern __shared__ char smraw[];
    __half* xs = reinterpret_cast<__half*>(smraw);            // [64][LDH]
    __half* ws = xs + XS_HALFS;                               // [128][LDH]
    float*  cs = reinterpret_cast<float*>(smraw);             // [64][LDC_S] (epilogue reuse)

    const bool is_gat = (blockIdx.y != 0);
    const float* W = is_gat ? gat_w : lin_w;
    const int n0 = blockIdx.x * 64;
    const int tid = threadIdx.x, wid = tid >> 5, lane = tid & 31;
    const int wr = wid & 1;          // warp row group: rows wr*32..wr*32+31
    const int wc = wid >> 1;         // warp col group: cols wc*32..wc*32+31

    // load x tile [64][128] fp32 -> fp16 smem
#pragma unroll
    for (int i = 0; i < 8; i++) {
        int f = tid + i * 256;               // float4 index over 64*32
        int row = f >> 5, c4 = f & 31;
        float4 v = make_float4(0.f, 0.f, 0.f, 0.f);
        if (n0 + row < N_NODES)
            v = reinterpret_cast<const float4*>(x)[(n0 + row) * 32 + c4];
        __half2 h0 = __floats2half2_rn(v.x, v.y);
        __half2 h1 = __floats2half2_rn(v.z, v.w);
        uint2 p;
        p.x = *reinterpret_cast<uint32_t*>(&h0);
        p.y = *reinterpret_cast<uint32_t*>(&h1);
        *reinterpret_cast<uint2*>(&xs[row * LDH + c4 * 4]) = p;
    }
    // load full W [128][128] fp32 -> fp16 smem (L2-resident after first blocks)
#pragma unroll
    for (int i = 0; i < 16; i++) {
        int f = tid + i * 256;
        int row = f >> 5, c4 = f & 31;
        float4 v = reinterpret_cast<const float4*>(W)[row * 32 + c4];
        __half2 h0 = __floats2half2_rn(v.x, v.y);
        __half2 h1 = __floats2half2_rn(v.z, v.w);
        uint2 p;
        p.x = *reinterpret_cast<uint32_t*>(&h0);
        p.y = *reinterpret_cast<uint32_t*>(&h1);
        *reinterpret_cast<uint2*>(&ws[row * LDH + c4 * 4]) = p;
    }
    __syncthreads();

    wmma::fragment<wmma::accumulator, 16, 16, 16, float> acc[2][2];
#pragma unroll
    for (int i = 0; i < 2; i++)
#pragma unroll
        for (int j = 0; j < 2; j++) wmma::fill_fragment(acc[i][j], 0.0f);

#pragma unroll
    for (int k = 0; k < 8; k++) {        // 8 k-steps of 16
        wmma::fragment<wmma::matrix_a, 16, 16, 16, __half, wmma::row_major> a[2];
        wmma::fragment<wmma::matrix_b, 16, 16, 16, __half, wmma::row_major> b[2];
#pragma unroll
        for (int i = 0; i < 2; i++)
            wmma::load_matrix_sync(a[i], &xs[(wr * 32 + i * 16) * LDH + k * 16], LDH);
#pragma unroll
        for (int j = 0; j < 2; j++)
            wmma::load_matrix_sync(b[j], &ws[(k * 16) * LDH + wc * 32 + j * 16], LDH);
#pragma unroll
        for (int i = 0; i < 2; i++)
#pragma unroll
            for (int j = 0; j < 2; j++)
                wmma::mma_sync(acc[i][j], a[i], b[j], acc[i][j]);
    }

    __syncthreads();                      // done with xs/ws; reuse as float C staging
#pragma unroll
    for (int i = 0; i < 2; i++)
#pragma unroll
        for (int j = 0; j < 2; j++)
            wmma::store_matrix_sync(&cs[(wr * 32 + i * 16) * LDC_S + wc * 32 + j * 16],
                                    acc[i][j], LDC_S, wmma::mem_row_major);
    __syncthreads();

    // epilogue: warp handles 8 rows; lane covers 4 cols (lane*4 .. lane*4+3)
    float4 b4 = make_float4(0.f, 0.f, 0.f, 0.f);
    float4 as4 = b4, ad4 = b4;
    if (is_gat) {
        as4 = *reinterpret_cast<const float4*>(&att_src[lane * 4]);
        ad4 = *reinterpret_cast<const float4*>(&att_dst[lane * 4]);
    } else {
        b4 = *reinterpret_cast<const float4*>(&lin_b[lane * 4]);
    }
    const int h = lane >> 3;     // head of this lane's columns
#pragma unroll
    for (int r = 0; r < 8; r++) {
        int row = wid * 8 + r;
        int n = n0 + row;
        float4 v = *reinterpret_cast<const float4*>(&cs[row * LDC_S + lane * 4]);
        if (!is_gat) {
            if (n < N_NODES) {
                v.x += b4.x; v.y += b4.y; v.z += b4.z; v.w += b4.w;
                *reinterpret_cast<float4*>(&g_hin[n * 128 + lane * 4]) = v;
            }
        } else {
            // logits from fp32 accumulators (before fp16 conversion)
            float s = v.x * as4.x + v.y * as4.y + v.z * as4.z + v.w * as4.w;
            float d = v.x * ad4.x + v.y * ad4.y + v.z * ad4.z + v.w * ad4.w;
#pragma unroll
            for (int o = 4; o > 0; o >>= 1) {      // reduce within 8-lane head group
                s += __shfl_xor_sync(0xffffffffu, s, o);
                d += __shfl_xor_sync(0xffffffffu, d, o);
            }
            if (n < N_NODES) {
                __half2 h0 = __floats2half2_rn(v.x, v.y);
                __half2 h1 = __floats2half2_rn(v.z, v.w);
                uint2 p;
                p.x = *reinterpret_cast<uint32_t*>(&h0);
                p.y = *reinterpret_cast<uint32_t*>(&h1);
                reinterpret_cast<uint2*>(g_xp)[n * 32 + lane] = p;  // 8B per lane
                if ((lane & 7) == 0) {
                    g_asrc[n * 4 + h] = s;
                    g_adst[n * 4 + h] = d;
                }
            }
        }
    }
}

// ---------------- K3: degree histogram ----------------
__global__ void count_kernel(const int* __restrict__ ei) {
    int i = blockIdx.x * blockDim.x + threadIdx.x;
    if (i >= M_EDGES) return;
    int d = (i < E_EDGES) ? ei[E_EDGES + i] : (i - E_EDGES);
    atomicAdd(&g_cnt[d], 1);
}

// ---------------- K4-K6: exclusive scan ----------------
__global__ void scanA_kernel() {
    __shared__ int sh[256];
    int t = threadIdx.x;
    int base = blockIdx.x * 1024 + t * 4;
    int v0 = 0, v1 = 0, v2 = 0, v3 = 0;
    if (base + 0 < N_NODES) v0 = g_cnt[base + 0];
    if (base + 1 < N_NODES) v1 = g_cnt[base + 1];
    if (base + 2 < N_NODES) v2 = g_cnt[base + 2];
    if (base + 3 < N_NODES) v3 = g_cnt[base + 3];
    int s = v0 + v1 + v2 + v3;
    sh[t] = s; __syncthreads();
    for (int off = 1; off < 256; off <<= 1) {
        int u = (t >= off) ? sh[t - off] : 0; __syncthreads();
        sh[t] += u; __syncthreads();
    }
    int run = sh[t] - s;
    if (base + 0 < N_NODES) g_rowstart[base + 0] = run; run += v0;
    if (base + 1 < N_NODES) g_rowstart[base + 1] = run; run += v1;
    if (base + 2 < N_NODES) g_rowstart[base + 2] = run; run += v2;
    if (base + 3 < N_NODES) g_rowstart[base + 3] = run;
    if (t == 255) g_blksum[blockIdx.x] = sh[255];
}

__global__ void scanB_kernel(int nb) {
    __shared__ int sh[256];
    int t = threadIdx.x;
    int v = (t < nb) ? g_blksum[t] : 0;
    sh[t] = v; __syncthreads();
    for (int off = 1; off < 256; off <<= 1) {
        int u = (t >= off) ? sh[t - off] : 0; __syncthreads();
        sh[t] += u; __syncthreads();
    }
    if (t < nb) g_blkoff[t] = sh[t] - v;
}

__global__ void scanC_kernel() {
    int t = threadIdx.x;
    int off = g_blkoff[blockIdx.x];
#pragma unroll
    for (int j = 0; j < 4; j++) {
        int i = blockIdx.x * 1024 + t * 4 + j;
        if (i < N_NODES) {
            int r = g_rowstart[i] + off;
            g_rowstart[i] = r;
            g_cursor[i] = r;
        }
    }
}

// ---------------- K7: scatter edges into CSR ----------------
__global__ void scatter_kernel(const int* __restrict__ ei) {
    int i = blockIdx.x * blockDim.x + threadIdx.x;
    if (i >= M_EDGES) return;
    int s, d;
    if (i < E_EDGES) { s = ei[i]; d = ei[E_EDGES + i]; }
    else             { s = d = i - E_EDGES; }
    int pos = atomicAdd(&g_cursor[d], 1);
    g_csr[pos] = s;
}

// ---------------- K8: TWO warps per node: single-pass softmax + agg + BN stats ----------------
// Warp pair splits the node's edge list; partial (acc, den) combined via smem.
// Identical math: acc = sum w_e*xp, den = sum w_e; combination just reassociates the sums.
// Block 256 thr = 8 warps = 4 node pairs. grid = ceil(N/4).
__global__ __launch_bounds__(256) void agg_kernel(const float* __restrict__ gat_bias,
                                                  float* __restrict__ out) {
    __shared__ float s_acc[4][32][5];    // [pair][lane][acc.xyzw, den]
    __shared__ float ssum[128];
    __shared__ float ssq[128];
    int tid = threadIdx.x;
    int wid = tid >> 5, lane = tid & 31;
    int pr = wid >> 1;                    // pair in block: 0..3
    int sub = wid & 1;                    // 0 = first half + finisher, 1 = second half
    int n = blockIdx.x * 4 + pr;
    if (tid < 128) { ssum[tid] = 0.f; ssq[tid] = 0.f; }
    __syncthreads();

    float4 acc = make_float4(0.f, 0.f, 0.f, 0.f);
    float den = 0.f;
    bool active = (n < N_NODES);
    int h = lane >> 3;
    float ad_h = 0.f;
    if (active) {
        int rs = g_rowstart[n];
        int deg = g_cnt[n];
        ad_h = g_adst[n * 4 + h];
        const uint2* xp2 = reinterpret_cast<const uint2*>(g_xp);

        // split edge range between the two warps of the pair
        int half = deg >> 1;
        int start = sub ? (rs + half) : rs;
        int fin   = sub ? (rs + deg)  : (rs + half);

        auto do1 = [&](int s) {
            float w = __expf(lrelu02(g_asrc[s * 4 + h] + ad_h));
            uint2 p = xp2[s * 32 + lane];
            float2 l = __half22float2(*reinterpret_cast<__half2*>(&p.x));
            float2 m = __half22float2(*reinterpret_cast<__half2*>(&p.y));
            den += w;
            acc.x += w * l.x; acc.y += w * l.y;
            acc.z += w * m.x; acc.w += w * m.y;
        };
        auto do4 = [&](int4 q) {
            float a0 = g_asrc[q.x * 4 + h], a1 = g_asrc[q.y * 4 + h];
            float a2 = g_asrc[q.z * 4 + h], a3 = g_asrc[q.w * 4 + h];
            uint2 p0 = xp2[q.x * 32 + lane];
            uint2 p1 = xp2[q.y * 32 + lane];
            uint2 p2 = xp2[q.z * 32 + lane];
            uint2 p3 = xp2[q.w * 32 + lane];
            float w0 = __expf(lrelu02(a0 + ad_h));
            float w1 = __expf(lrelu02(a1 + ad_h));
            float w2 = __expf(lrelu02(a2 + ad_h));
            float w3 = __expf(lrelu02(a3 + ad_h));
            den += (w0 + w1) + (w2 + w3);
            float2 l0 = __half22float2(*reinterpret_cast<__half2*>(&p0.x));
            float2 m0 = __half22float2(*reinterpret_cast<__half2*>(&p0.y));
            float2 l1 = __half22float2(*reinterpret_cast<__half2*>(&p1.x));
            float2 m1 = __half22float2(*reinterpret_cast<__half2*>(&p1.y));
            float2 l2 = __half22float2(*reinterpret_cast<__half2*>(&p2.x));
            float2 m2 = __half22float2(*reinterpret_cast<__half2*>(&p2.y));
            float2 l3 = __half22float2(*reinterpret_cast<__half2*>(&p3.x));
            float2 m3 = __half22float2(*reinterpret_cast<__half2*>(&p3.y));
            acc.x += w0 * l0.x + w1 * l1.x + w2 * l2.x + w3 * l3.x;
            acc.y += w0 * l0.y + w1 * l1.y + w2 * l2.y + w3 * l3.y;
            acc.z += w0 * m0.x + w1 * m1.x + w2 * m2.x + w3 * m3.x;
            acc.w += w0 * m0.y + w1 * m1.y + w2 * m2.y + w3 * m3.y;
        };

        int e = start;
        while (e < fin && (e & 3)) { do1(g_csr[e]); e++; }      // align to 16B
        for (; e + 8 <= fin; e += 8) {                           // 2x int4
            int4 qa = *reinterpret_cast<const int4*>(&g_csr[e]);
            int4 qb = *reinterpret_cast<const int4*>(&g_csr[e + 4]);
            do4(qa);
            do4(qb);
        }
        if (e + 4 <= fin) {
            do4(*reinterpret_cast<const int4*>(&g_csr[e]));
            e += 4;
        }
        for (; e < fin; e++) do1(g_csr[e]);

        if (sub == 1) {                   // publish partial
            s_acc[pr][lane][0] = acc.x;
            s_acc[pr][lane][1] = acc.y;
            s_acc[pr][lane][2] = acc.z;
            s_acc[pr][lane][3] = acc.w;
            s_acc[pr][lane][4] = den;
        }
    }
    __syncthreads();

    if (active && sub == 0) {             // combine + finish
        acc.x += s_acc[pr][lane][0];
        acc.y += s_acc[pr][lane][1];
        acc.z += s_acc[pr][lane][2];
        acc.w += s_acc[pr][lane][3];
        den   += s_acc[pr][lane][4];
        float inv = 1.0f / den;           // den > 0 guaranteed by self loop
        float4 b = reinterpret_cast<const float4*>(gat_bias)[lane];
        acc.x = acc.x * inv + b.x; acc.y = acc.y * inv + b.y;
        acc.z = acc.z * inv + b.z; acc.w = acc.w * inv + b.w;
        reinterpret_cast<float4*>(out)[n * 32 + lane] = acc;

        atomicAdd(&ssum[lane * 4 + 0], acc.x);
        atomicAdd(&ssum[lane * 4 + 1], acc.y);
        atomicAdd(&ssum[lane * 4 + 2], acc.z);
        atomicAdd(&ssum[lane * 4 + 3], acc.w);
        atomicAdd(&ssq[lane * 4 + 0], acc.x * acc.x);
        atomicAdd(&ssq[lane * 4 + 1], acc.y * acc.y);
        atomicAdd(&ssq[lane * 4 + 2], acc.z * acc.z);
        atomicAdd(&ssq[lane * 4 + 3], acc.w * acc.w);
    }
    __syncthreads();
    if (tid < 128) {
        atomicAdd(&g_colsum[tid], ssum[tid]);
        atomicAdd(&g_colsumsq[tid], ssq[tid]);
    }
}

// ---------------- K10: BN + ELU + residual (float4) ----------------
__global__ void final_kernel(float* __restrict__ out,
                             const float* __restrict__ gamma, const float* __restrict__ beta) {
    int i = blockIdx.x * blockDim.x + threadIdx.x;   // over N*32 float4s
    if (i >= N_NODES * 32) return;
    int c4 = i & 31;
    const float invN = 1.0f / (float)N_NODES;
    float4 cs = reinterpret_cast<const float4*>(g_colsum)[c4];
    float4 cq = reinterpret_cast<const float4*>(g_colsumsq)[c4];
    float4 gm = reinterpret_cast<const float4*>(gamma)[c4];
    float4 bt = reinterpret_cast<const float4*>(beta)[c4];
    float4 y  = reinterpret_cast<const float4*>(out)[i];
    float4 hv = reinterpret_cast<const float4*>(g_hin)[i];
    float4 r;
    {
        float mu = cs.x * invN, var = cq.x * invN - mu * mu;
        float t = (y.x - mu) * rsqrtf(var + 1e-5f) * gm.x + bt.x;
        r.x = hv.x + (t > 0.f ? t : expm1f(t));
    }
    {
        float mu = cs.y * invN, var = cq.y * invN - mu * mu;
        float t = (y.y - mu) * rsqrtf(var + 1e-5f) * gm.y + bt.y;
        r.y = hv.y + (t > 0.f ? t : expm1f(t));
    }
    {
        float mu = cs.z * invN, var = cq.z * invN - mu * mu;
        float t = (y.z - mu) * rsqrtf(var + 1e-5f) * gm.z + bt.z;
        r.z = hv.z + (t > 0.f ? t : expm1f(t));
    }
    {
        float mu = cs.w * invN, var = cq.w * invN - mu * mu;
        float t = (y.w - mu) * rsqrtf(var + 1e-5f) * gm.w + bt.w;
        r.w = hv.w + (t > 0.f ? t : expm1f(t));
    }
    reinterpret_cast<float4*>(out)[i] = r;
}

// ---------------- launch: forked graph (gemm || edge-CSR pipeline) ----------------
extern "C" void kernel_launch(void* const* d_in, const int* in_sizes, int n_in,
                              void* d_out, int out_size) {
    const float* x        = (const float*)d_in[0];
    const int*   ei       = (const int*)  d_in[1];
    const float* lin_w    = (const float*)d_in[2];
    const float* lin_b    = (const float*)d_in[3];
    const float* gat_w    = (const float*)d_in[4];
    const float* att_src  = (const float*)d_in[5];
    const float* att_dst  = (const float*)d_in[6];
    const float* gat_bias = (const float*)d_in[7];
    const float* bn_gamma = (const float*)d_in[8];
    const float* bn_beta  = (const float*)d_in[9];
    float* out = (float*)d_out;

    cudaFuncSetAttribute(gemm_kernel, cudaFuncAttributeMaxDynamicSharedMemorySize, GEMM_SMEM);

    const int NB = (N_NODES + 1023) / 1024;

    // host-side objects: created during the (single) capture call only; replays
    // execute the captured graph, not this host code.
    cudaStream_t sB;
    cudaStreamCreateWithFlags(&sB, cudaStreamNonBlocking);
    cudaEvent_t evFork, evJoin;
    cudaEventCreateWithFlags(&evFork, cudaEventDisableTiming);
    cudaEventCreateWithFlags(&evJoin, cudaEventDisableTiming);

    // fork: edge pipeline branch (independent of gemm)
    cudaEventRecord(evFork, 0);
    cudaStreamWaitEvent(sB, evFork, 0);

    // main branch: dense GEMM (+ logits)
    gemm_kernel<<<dim3((N_NODES + 63) / 64, 2), 256, GEMM_SMEM, 0>>>(
        x, lin_w, lin_b, gat_w, att_src, att_dst);

    // edge branch: init -> histogram -> scan -> scatter (CSR build)
    init_kernel<<<(N_NODES + 255) / 256, 256, 0, sB>>>();
    count_kernel<<<(M_EDGES + 255) / 256, 256, 0, sB>>>(ei);
    scanA_kernel<<<NB, 256, 0, sB>>>();
    scanB_kernel<<<1, 256, 0, sB>>>(NB);
    scanC_kernel<<<NB, 256, 0, sB>>>();
    scatter_kernel<<<(M_EDGES + 255) / 256, 256, 0, sB>>>(ei);

    // join
    cudaEventRecord(evJoin, sB);
    cudaStreamWaitEvent(0, evJoin, 0);

    agg_kernel<<<(N_NODES + 3) / 4, 256, 0, 0>>>(gat_bias, out);
    final_kernel<<<(N_NODES * 32 + 255) / 256, 256, 0, 0>>>(out, bn_gamma, bn_beta);
}